// round 13
// baseline (speedup 1.0000x reference)
#include <cuda_runtime.h>
#include <cstdint>

#define BATCH 16
#define CC 80
#define NN 16384              // locations per batch
#define NC (NN*CC)            // 1310720 candidates per batch
#define TOPN_ 1000
#define NBINS 4096            // histogram bins over [0.6, 1)
#define HLO 0.6f
#define SCALE ((float)NBINS / 0.4f)   // 10240
#define CAP1 131072           // stage-1 candidate capacity per batch (expected ~36K)
#define SORTN 2048            // key buffer per batch (typical winners ~1008)
#define QUADS_PER_BATCH (NC/4)        // 327680
#define LPB 128               // locations per pass1 block
#define BPB 128               // pass1 blocks per batch
#define NT 256                // pass1/gather threads per block
#define NWARP 8
#define EBUF 192              // per-warp element buffer (expect ~38, ~20-sigma margin)
#define GSLICE 8              // gather blocks per batch

// ------------------------- scratch (zero-initialized at module load; ---------
// ------------------------- self-cleaned by k_snd every run) -------------------
__device__ int    g_hist[BATCH*NBINS];
__device__ int    g_cnt1[BATCH];
__device__ int    g_cnt2[BATCH];
__device__ unsigned long long g_cand1[(size_t)BATCH*CAP1];
__device__ unsigned long long g_keys2[BATCH*SORTN];

__device__ __forceinline__ float sigmoidf_(float x){ return 1.0f/(1.0f + expf(-x)); }

// one bitonic compare-exchange step done in registers via shfl_xor.
// desc region ⇔ (p & k)==0 — same orientation as the smem steps.
__device__ __forceinline__ unsigned long long
regstep(unsigned long long e, int p, int k, int j){
    unsigned long long partner = __shfl_xor_sync(0xffffffffu, e, j);
    bool desc  = ((p & k) == 0);
    bool lower = ((p & j) == 0);
    unsigned long long mx = (e > partner) ? e : partner;
    unsigned long long mn = (e > partner) ? partner : e;
    return (desc == lower) ? mx : mn;
}

// ------------------------- K1: single heavy pass over pred_cls ----------------
// Compact-then-compute: the streaming loop does only fmax-tree + threshold
// compares, pushing raw {logit, idx} records of xth-passing elements (~3%)
// into per-warp smem buffers. A dense phase-B then re-scores them at full
// warp occupancy (exact sigmoid, bit-identical to prior rounds), builds the
// histogram, and appends keys straight to global via ballot aggregation.
__global__ void __launch_bounds__(NT, 6)
k_pass1(const float* __restrict__ cls, const float* __restrict__ pctr){
    int b   = blockIdx.x >> 7;          // /BPB
    int blk = blockIdx.x & (BPB-1);
    int loc0 = blk * LPB;
    int tid = threadIdx.x, lane = tid & 31, wid = tid >> 5;

    __shared__ float s_ctr[LPB];
    __shared__ float s_xth[LPB];
    __shared__ uint2 s_ebuf[NWARP][EBUF];   // {logit bits, local element idx} — 12 KB
    __shared__ int   s_en[NWARP];

    if (tid < NWARP) s_en[tid] = 0;
    if (tid < LPB){
        float sg = sigmoidf_(pctr[b*NN + loc0 + tid]);
        float xth = 3.3e38f;
        if (sg > HLO){
            float q = HLO / sg;                   // in (0.6, 1)
            xth = __logf(q/(1.0f-q)) - 1e-3f;     // conservative margin
        }
        s_ctr[tid] = sg;
        s_xth[tid] = xth;
    }
    __syncthreads();

    const float4* p = reinterpret_cast<const float4*>(cls)
                    + (size_t)b*QUADS_PER_BATCH + (size_t)loc0*20;

    // ---- phase A: stream + compact (no MUFU, no atomics beyond the push) ----
    #pragma unroll
    for (int hh = 0; hh < 2; hh++){
        float4 v[5];
        #pragma unroll
        for (int j = 0; j < 5; j++)
            v[j] = __ldcs(&p[(hh*5 + j)*NT + tid]);     // streaming, read-once
        #pragma unroll
        for (int j = 0; j < 5; j++){
            int q = (hh*5 + j)*NT + tid;                // [0, 2560)
            float xth = s_xth[q/20];
            float mx = fmaxf(fmaxf(v[j].x, v[j].y), fmaxf(v[j].z, v[j].w));
            if (mx > xth){                              // ~11% of quads
                float xs[4] = {v[j].x, v[j].y, v[j].z, v[j].w};
                #pragma unroll
                for (int k = 0; k < 4; k++){
                    if (xs[k] > xth){                   // ~3% of elements
                        int pos = atomicAdd(&s_en[wid], 1);   // per-warp bank
                        if (pos < EBUF)
                            s_ebuf[wid][pos] =
                                make_uint2(__float_as_uint(xs[k]), (unsigned)(q*4 + k));
                    }
                }
            }
        }
    }
    __syncwarp();

    // ---- phase B: dense re-scoring of this warp's buffered elements ----
    int en = s_en[wid]; if (en > EBUF) en = EBUF;
    int* hist = g_hist + b*NBINS;
    for (int i0 = 0; i0 < en; i0 += 32){
        int i = i0 + lane;
        bool win = false;
        unsigned long long key = 0ull;
        int bin = 0;
        if (i < en){
            uint2 e = s_ebuf[wid][i];
            float x = __uint_as_float(e.x);
            int il = (int)e.y;                   // local element idx in [0,10240)
            float ctr = s_ctr[il/80];
            float s1 = sigmoidf_(x);
            float sc = s1 * ctr;
            if (sc >= HLO){
                win = true;
                unsigned idx = (unsigned)(loc0*80 + il);     // global in-batch idx
                key = ((unsigned long long)__float_as_uint(sc) << 21)
                    | (unsigned long long)(0x1FFFFFu - idx);
                bin = (int)((sc - HLO) * SCALE);
                if (bin > NBINS-1) bin = NBINS-1;
            }
        }
        if (win) atomicAdd(&hist[bin], 1);               // RED, scattered
        unsigned bal = __ballot_sync(0xffffffffu, win);
        if (bal){
            int leader = __ffs(bal) - 1;
            int base = 0;
            if (lane == leader) base = atomicAdd(&g_cnt1[b], __popc(bal));
            base = __shfl_sync(0xffffffffu, base, leader);
            if (win){
                int pos = base + __popc(bal & ((1u << lane) - 1u));
                if (pos < CAP1) g_cand1[(size_t)b*CAP1 + pos] = key;
            }
        }
    }
}

// ------------------------- K2: cutoff (per-block, redundant) + gather ---------
// 8 blocks per batch. Each block recomputes the cutoff bin from the 4096-bin
// histogram (16 KB, L2-hit) then gathers its slice of above-cutoff candidates
// via ballot-aggregated global appends (order irrelevant; sorted next).
__global__ void __launch_bounds__(NT)
k_gather(){
    int b = blockIdx.x >> 3, slice = blockIdx.x & (GSLICE-1);
    int tid = threadIdx.x, lane = tid & 31, wid = tid >> 5;
    __shared__ int S[NT];
    __shared__ int s_wtot[NWARP], s_wexc[NWARP];
    __shared__ int s_g, s_cut;

    const int* hist = g_hist + b*NBINS;
    int s = 0;
    #pragma unroll
    for (int k = 0; k < 16; k++) s += hist[tid*16 + k];
    int v = s;                                       // intra-warp inclusive suffix
    #pragma unroll
    for (int off = 1; off < 32; off <<= 1){
        int u = __shfl_down_sync(0xffffffffu, v, off);
        if (lane + off < 32) v += u;
    }
    if (lane == 0) s_wtot[wid] = v;
    if (tid == 0) s_g = -1;
    __syncthreads();
    if (tid == 0){
        int acc = 0;
        #pragma unroll
        for (int w = NWARP-1; w >= 0; w--){ s_wexc[w] = acc; acc += s_wtot[w]; }
    }
    __syncthreads();
    int T = v + s_wexc[wid];
    S[tid] = T;
    __syncthreads();
    if (T >= TOPN_ && (tid == NT-1 || S[tid+1] < TOPN_)) s_g = tid;
    __syncthreads();
    if (tid == 0 && s_g < 0) s_cut = 0;
    if (s_g >= 0 && tid == s_g){
        int cum = (tid == NT-1) ? 0 : S[tid+1];
        int bin = tid*16 + 15;
        for (; bin >= tid*16; bin--){
            cum += hist[bin];
            if (cum >= TOPN_) break;
        }
        if (bin < tid*16) bin = tid*16;
        s_cut = bin;
    }
    __syncthreads();
    int cut = s_cut;

    int cnt1 = g_cnt1[b]; if (cnt1 > CAP1) cnt1 = CAP1;
    int per = (cnt1 + GSLICE-1) / GSLICE;
    int start = slice*per, end = min(start + per, cnt1);
    const unsigned long long* gc = g_cand1 + (size_t)b*CAP1;
    for (int i = start + tid; i < end; i += NT){
        unsigned long long key = gc[i];
        float sc = __uint_as_float((unsigned)(key >> 21));
        int bin = (int)((sc - HLO) * SCALE);
        if (bin > NBINS-1) bin = NBINS-1;
        bool win = (bin >= cut);
        unsigned bal = __ballot_sync(__activemask(), win);
        if (bal){
            int leader = __ffs(bal) - 1;
            int base = 0;
            if (lane == leader) base = atomicAdd(&g_cnt2[b], __popc(bal));
            base = __shfl_sync(__activemask(), base, leader);
            if (win){
                int pos = base + __popc(bal & ((1u << lane) - 1u));
                if (pos < SORTN) g_keys2[b*SORTN + pos] = key;
            }
        }
    }
}

// ------------------------- K3: sort + decode + NMS + output + self-clean -----
// One block per batch, 1024 threads. 1024-key sort common path (cnt2<=1024 whp,
// 2048 fallback). NMS entirely smem-resident. Single-pass class collect.
__global__ void __launch_bounds__(1024, 1)
k_snd(const float* __restrict__ boxes, const float* __restrict__ loc,
      float* __restrict__ out){
    int b = blockIdx.x, tid = threadIdx.x, lane = tid & 31, wid = tid >> 5;

    __shared__ unsigned long long s_keys[SORTN];  // 16 KB
    __shared__ float4 s_det[TOPN_];               // 16 KB
    __shared__ unsigned char s_lab[TOPN_];
    __shared__ unsigned char s_keep[TOPN_];
    __shared__ int   s_order[TOPN_];              // 4 KB
    __shared__ int   s_ccnt[CC];
    __shared__ int   s_coff[CC];

    int cnt2 = g_cnt2[b]; if (cnt2 > SORTN) cnt2 = SORTN;   // block-uniform
    bool big = (cnt2 > 1024);
    s_keys[tid] = (tid < cnt2) ? g_keys2[b*SORTN + tid] : 0ull;
    s_keys[1024 + tid] = (big && 1024 + tid < cnt2) ? g_keys2[b*SORTN + 1024 + tid] : 0ull;
    if (tid < CC) s_ccnt[tid] = 0;
    __syncthreads();

    if (!big){
        // ---- 1024-key hybrid bitonic, warps 0..15 own 64-element chunks ----
        if (wid < 16){
            int p0 = (wid << 6) + lane, p1 = p0 + 32;
            unsigned long long e0 = s_keys[p0], e1 = s_keys[p1];
            #pragma unroll
            for (int k = 2; k <= 32; k <<= 1){
                #pragma unroll
                for (int j = k >> 1; j > 0; j >>= 1){
                    e0 = regstep(e0, p0, k, j);
                    e1 = regstep(e1, p1, k, j);
                }
            }
            {   // k = 64: j=32 in-thread swap + shfl tail
                bool desc = ((p0 & 64) == 0);
                unsigned long long mx = (e0 > e1) ? e0 : e1;
                unsigned long long mn = (e0 > e1) ? e1 : e0;
                e0 = desc ? mx : mn;  e1 = desc ? mn : mx;
                #pragma unroll
                for (int j = 16; j > 0; j >>= 1){
                    e0 = regstep(e0, p0, 64, j);
                    e1 = regstep(e1, p1, 64, j);
                }
            }
            s_keys[p0] = e0; s_keys[p1] = e1;
        }
        for (int k = 128; k <= 1024; k <<= 1){
            for (int j = k >> 1; j >= 64; j >>= 1){
                __syncthreads();
                if (tid < 512){
                    int idx = ((tid & ~(j-1)) << 1) | (tid & (j-1));
                    int pr  = idx | j;
                    unsigned long long a = s_keys[idx], c = s_keys[pr];
                    bool up = (idx & k) == 0;
                    if (up ? (a < c) : (a > c)){ s_keys[idx] = c; s_keys[pr] = a; }
                }
            }
            __syncthreads();
            if (wid < 16){
                int p0 = (wid << 6) + lane, p1 = p0 + 32;
                unsigned long long e0 = s_keys[p0], e1 = s_keys[p1];
                bool desc = ((p0 & k) == 0);
                unsigned long long mx = (e0 > e1) ? e0 : e1;
                unsigned long long mn = (e0 > e1) ? e1 : e0;
                e0 = desc ? mx : mn;  e1 = desc ? mn : mx;
                #pragma unroll
                for (int j = 16; j > 0; j >>= 1){
                    e0 = regstep(e0, p0, k, j);
                    e1 = regstep(e1, p1, k, j);
                }
                s_keys[p0] = e0; s_keys[p1] = e1;
            }
        }
        __syncthreads();
    } else {
        // ---- full 2048-key hybrid bitonic (rare fallback) ----
        int p0 = (wid << 6) + lane, p1 = p0 + 32;
        unsigned long long e0 = s_keys[p0], e1 = s_keys[p1];
        #pragma unroll
        for (int k = 2; k <= 32; k <<= 1){
            #pragma unroll
            for (int j = k >> 1; j > 0; j >>= 1){
                e0 = regstep(e0, p0, k, j);
                e1 = regstep(e1, p1, k, j);
            }
        }
        {
            bool desc = ((p0 & 64) == 0);
            unsigned long long mx = (e0 > e1) ? e0 : e1;
            unsigned long long mn = (e0 > e1) ? e1 : e0;
            e0 = desc ? mx : mn;  e1 = desc ? mn : mx;
            #pragma unroll
            for (int j = 16; j > 0; j >>= 1){
                e0 = regstep(e0, p0, 64, j);
                e1 = regstep(e1, p1, 64, j);
            }
        }
        s_keys[p0] = e0; s_keys[p1] = e1;
        for (int k = 128; k <= SORTN; k <<= 1){
            for (int j = k >> 1; j >= 64; j >>= 1){
                __syncthreads();
                int idx = ((tid & ~(j-1)) << 1) | (tid & (j-1));
                int pr  = idx | j;
                unsigned long long a = s_keys[idx], c = s_keys[pr];
                bool up = (idx & k) == 0;
                if (up ? (a < c) : (a > c)){ s_keys[idx] = c; s_keys[pr] = a; }
            }
            __syncthreads();
            e0 = s_keys[p0]; e1 = s_keys[p1];
            bool desc = ((p0 & k) == 0);
            unsigned long long mx = (e0 > e1) ? e0 : e1;
            unsigned long long mn = (e0 > e1) ? e1 : e0;
            e0 = desc ? mx : mn;  e1 = desc ? mn : mx;
            #pragma unroll
            for (int j = 16; j > 0; j >>= 1){
                e0 = regstep(e0, p0, k, j);
                e1 = regstep(e1, p1, k, j);
            }
            s_keys[p0] = e0; s_keys[p1] = e1;
        }
        __syncthreads();
    }

    // ---- decode top-1000 (+ per-class counts in the same pass) ----
    if (tid < TOPN_){
        unsigned long long key = s_keys[tid];
        s_keep[tid] = 0;
        if (key == 0ull){
            s_det[tid] = make_float4(0.f,0.f,0.f,0.f);
            s_lab[tid] = 0;
        } else {
            unsigned idx = 0x1FFFFFu - (unsigned)(key & 0x1FFFFFu);
            int n = idx / CC, c = idx % CC;
            float4 pb = reinterpret_cast<const float4*>(boxes)[(size_t)b*NN + n];
            float2 l = reinterpret_cast<const float2*>(loc)[n];
            float x1 = fminf(fmaxf(l.x - pb.x, 0.0f), 1023.0f);
            float y1 = fminf(fmaxf(l.y - pb.y, 0.0f), 1023.0f);
            float x2 = fminf(fmaxf(l.x + pb.z, 0.0f), 1023.0f);
            float y2 = fminf(fmaxf(l.y + pb.w, 0.0f), 1023.0f);
            s_det[tid] = make_float4(x1, y1, x2, y2);
            s_lab[tid] = (unsigned char)(c + 1);
            atomicAdd(&s_ccnt[c], 1);
        }
    }
    // self-clean pipeline state while decode settles
    {
        int* hist = g_hist + b*NBINS;
        #pragma unroll
        for (int k = 0; k < NBINS/1024; k++) hist[k*1024 + tid] = 0;
        if (tid == 0){ g_cnt1[b] = 0; g_cnt2[b] = 0; }
    }
    __syncthreads();
    if (tid == 0){
        int acc = 0;
        for (int c = 0; c < CC; c++){ s_coff[c] = acc; acc += s_ccnt[c]; }
    }
    __syncthreads();

    // ---- per-class greedy NMS (class offsets => cross-class IoU = 0) ----
    // One warp per class (2.5 classes/warp); single write-collect pass.
    for (int c = wid; c < CC; c += 32){
        int off = s_coff[c];
        int m = 0;
        for (int k0 = 0; k0 < TOPN_; k0 += 32){
            int k = k0 + lane;
            bool match = (k < TOPN_) && (s_lab[k] == (unsigned char)(c+1));
            unsigned bal = __ballot_sync(0xffffffffu, match);
            if (match){
                int pos = m + __popc(bal & ((1u << lane) - 1u));
                s_order[off + pos] = k;       // ranks in descending-score order
            }
            m += __popc(bal);
        }
        float co = (float)(c+1) * 4096.0f;
        unsigned aliveM = 0xffffffffu;        // bit s2 => entry e = s2*32+lane alive
        int Sl = (m + 31) >> 5;
        for (int i = 0; i < m; i++){
            int owner = i & 31, slot = i >> 5;
            unsigned a = __shfl_sync(0xffffffffu, aliveM, owner);
            if (!((a >> slot) & 1u)) continue;         // warp-uniform
            float4 bi = s_det[s_order[off + i]];
            bi.x += co; bi.y += co; bi.z += co; bi.w += co;
            float ai = fmaxf(bi.z - bi.x, 0.f) * fmaxf(bi.w - bi.y, 0.f);
            for (int s2 = 0; s2 < Sl; s2++){
                int e = (s2 << 5) + lane;
                if (e > i && e < m && ((aliveM >> s2) & 1u)){
                    float4 bj = s_det[s_order[off + e]];
                    bj.x += co; bj.y += co; bj.z += co; bj.w += co;
                    float aj = fmaxf(bj.z - bj.x, 0.f) * fmaxf(bj.w - bj.y, 0.f);
                    float ix1 = fmaxf(bi.x, bj.x), iy1 = fmaxf(bi.y, bj.y);
                    float ix2 = fminf(bi.z, bj.z), iy2 = fminf(bi.w, bj.w);
                    float inter = fmaxf(ix2 - ix1, 0.f) * fmaxf(iy2 - iy1, 0.f);
                    float iou = inter / ((ai + aj - inter) + 1e-9f);
                    if (iou > 0.6f) aliveM &= ~(1u << s2);
                }
            }
        }
        for (int s2 = 0; s2 < Sl; s2++){
            int e = (s2 << 5) + lane;
            if (e < m) s_keep[s_order[off + e]] = (unsigned char)((aliveM >> s2) & 1u);
        }
    }
    __syncthreads();

    // ---- write output [boxes 16*1000*4][scores 16*1000][labels] ----
    if (tid < TOPN_){
        int t = b*TOPN_ + tid;
        int kp = s_keep[tid];
        float kf = kp ? 1.0f : 0.0f;
        float4 d = s_det[tid];
        reinterpret_cast<float4*>(out)[t] =
            make_float4(d.x*kf, d.y*kf, d.z*kf, d.w*kf);
        unsigned long long key = s_keys[tid];
        out[BATCH*TOPN_*4 + t] = kp ? __uint_as_float((unsigned)(key >> 21)) : 0.0f;
        out[BATCH*TOPN_*5 + t] = kp ? (float)s_lab[tid] : 0.0f;
    }
}

// ------------------------- launch ---------------------------------------------
extern "C" void kernel_launch(void* const* d_in, const int* in_sizes, int n_in,
                              void* d_out, int out_size){
    const float* locations  = (const float*)d_in[0];
    const float* pred_cls   = (const float*)d_in[1];
    const float* pred_boxes = (const float*)d_in[2];
    const float* pred_ctr   = (const float*)d_in[3];
    float* out = (float*)d_out;

    k_pass1 <<<BATCH*BPB, NT>>>(pred_cls, pred_ctr);
    k_gather<<<BATCH*GSLICE, NT>>>();
    k_snd   <<<BATCH, 1024>>>(pred_boxes, locations, out);
}

// round 16
// speedup vs baseline: 1.3200x; 1.3200x over previous
#include <cuda_runtime.h>
#include <cstdint>

#define BATCH 16
#define CC 80
#define NN 16384              // locations per batch
#define NC (NN*CC)            // 1310720 candidates per batch
#define TOPN_ 1000
#define NBINS 4096            // histogram bins over [0.6, 1)
#define HLO 0.6f
#define SCALE ((float)NBINS / 0.4f)   // 10240
#define CAP1 131072           // stage-1 candidate capacity per batch (expected ~36K)
#define SORTN 2048            // key buffer per batch (typical winners ~1008)
#define QUADS_PER_BATCH (NC/4)        // 327680
#define LPB 128               // locations per pass1 block
#define BPB 128               // pass1 blocks per batch
#define NT 256                // pass1/gather threads per block
#define NWARP 8
#define WBUF 192              // per-warp candidate buffer (expect ~36, 21-sigma margin)
#define GSLICE 8              // gather blocks per batch
#define NMSB 4                // NMS sub-blocks per batch (20 classes each)

// ------------------------- scratch (zero-initialized at module load; ---------
// ------------------------- self-cleaned by k_snd sub==0 every run) ------------
__device__ int    g_hist[BATCH*NBINS];
__device__ int    g_cnt1[BATCH];
__device__ int    g_cnt2[BATCH];
__device__ unsigned long long g_cand1[(size_t)BATCH*CAP1];
__device__ unsigned long long g_keys2[BATCH*SORTN];

__device__ __forceinline__ float sigmoidf_(float x){ return 1.0f/(1.0f + expf(-x)); }

// one bitonic compare-exchange step done in registers via shfl_xor.
// desc region ⇔ (p & k)==0 — same orientation as the smem steps.
__device__ __forceinline__ unsigned long long
regstep(unsigned long long e, int p, int k, int j){
    unsigned long long partner = __shfl_xor_sync(0xffffffffu, e, j);
    bool desc  = ((p & k) == 0);
    bool lower = ((p & j) == 0);
    unsigned long long mx = (e > partner) ? e : partner;
    unsigned long long mn = (e > partner) ? partner : e;
    return (desc == lower) ? mx : mn;
}

// ------------------------- K1: single heavy pass over pred_cls ----------------
// Byte-exact R12 version (measured 28.1us, best known).
__global__ void __launch_bounds__(NT, 6)
k_pass1(const float* __restrict__ cls, const float* __restrict__ pctr){
    int b   = blockIdx.x >> 7;          // /BPB
    int blk = blockIdx.x & (BPB-1);
    int loc0 = blk * LPB;
    int tid = threadIdx.x, lane = tid & 31, wid = tid >> 5;

    __shared__ float2 s_thr[LPB];                       // {ctr_sigmoid, xth}
    __shared__ unsigned long long s_wbuf[NWARP][WBUF];  // 12 KB
    __shared__ int s_wn[NWARP];
    __shared__ int s_woff[NWARP];
    __shared__ int s_base;

    if (tid < NWARP) s_wn[tid] = 0;
    if (tid < LPB){
        float sg = sigmoidf_(pctr[b*NN + loc0 + tid]);
        float xth = 3.3e38f;
        if (sg > HLO){
            float q = HLO / sg;                   // in (0.6, 1)
            xth = __logf(q/(1.0f-q)) - 1e-3f;     // conservative margin
        }
        s_thr[tid] = make_float2(sg, xth);
    }
    __syncthreads();

    const float4* p = reinterpret_cast<const float4*>(cls)
                    + (size_t)b*QUADS_PER_BATCH + (size_t)loc0*20;
    int* hist = g_hist + b*NBINS;

    #pragma unroll
    for (int hh = 0; hh < 2; hh++){
        float4 v[5];
        #pragma unroll
        for (int j = 0; j < 5; j++)
            v[j] = __ldcs(&p[(hh*5 + j)*NT + tid]);     // streaming, read-once
        #pragma unroll
        for (int j = 0; j < 5; j++){
            int q = (hh*5 + j)*NT + tid;                // [0, 2560)
            float2 tc = s_thr[q/20];                    // x = ctr, y = xth
            float mx = fmaxf(fmaxf(v[j].x, v[j].y), fmaxf(v[j].z, v[j].w));
            if (mx > tc.y){                             // rare (~17% of quads)
                float xs[4] = {v[j].x, v[j].y, v[j].z, v[j].w};
                #pragma unroll
                for (int k = 0; k < 4; k++){
                    if (xs[k] > tc.y){
                        float s1 = sigmoidf_(xs[k]);
                        float sc = s1 * tc.x;
                        if (sc >= HLO){
                            unsigned idx = (unsigned)((loc0*20 + q)*4 + k);
                            int pos = atomicAdd(&s_wn[wid], 1);   // per-warp bank
                            if (pos < WBUF)
                                s_wbuf[wid][pos] =
                                    ((unsigned long long)__float_as_uint(sc) << 21)
                                  | (unsigned long long)(0x1FFFFFu - idx);
                            int bin = (int)((sc - HLO) * SCALE);
                            if (bin > NBINS-1) bin = NBINS-1;
                            atomicAdd(&hist[bin], 1);             // RED, scattered
                        }
                    }
                }
            }
        }
    }
    __syncthreads();
    if (tid == 0){
        int acc = 0;
        #pragma unroll
        for (int w = 0; w < NWARP; w++){
            int c = s_wn[w]; if (c > WBUF) c = WBUF;
            s_woff[w] = acc; acc += c;
        }
        s_base = atomicAdd(&g_cnt1[b], acc);
    }
    __syncthreads();
    {
        int wn = s_wn[wid]; if (wn > WBUF) wn = WBUF;
        int seg = s_base + s_woff[wid];
        for (int i = lane; i < wn; i += 32){
            int pos = seg + i;
            if (pos < CAP1) g_cand1[(size_t)b*CAP1 + pos] = s_wbuf[wid][i];
        }
    }
}

// ------------------------- K2: cutoff (per-block, redundant) + gather ---------
// 8 blocks per batch; redundant cutoff from the 4096-bin histogram (L2-hit),
// then ballot-aggregated global appends of above-cutoff candidates.
__global__ void __launch_bounds__(NT)
k_gather(){
    int b = blockIdx.x >> 3, slice = blockIdx.x & (GSLICE-1);
    int tid = threadIdx.x, lane = tid & 31, wid = tid >> 5;
    __shared__ int S[NT];
    __shared__ int s_wtot[NWARP], s_wexc[NWARP];
    __shared__ int s_g, s_cut;

    const int* hist = g_hist + b*NBINS;
    int s = 0;
    #pragma unroll
    for (int k = 0; k < 16; k++) s += hist[tid*16 + k];
    int v = s;                                       // intra-warp inclusive suffix
    #pragma unroll
    for (int off = 1; off < 32; off <<= 1){
        int u = __shfl_down_sync(0xffffffffu, v, off);
        if (lane + off < 32) v += u;
    }
    if (lane == 0) s_wtot[wid] = v;
    if (tid == 0) s_g = -1;
    __syncthreads();
    if (tid == 0){
        int acc = 0;
        #pragma unroll
        for (int w = NWARP-1; w >= 0; w--){ s_wexc[w] = acc; acc += s_wtot[w]; }
    }
    __syncthreads();
    int T = v + s_wexc[wid];
    S[tid] = T;
    __syncthreads();
    if (T >= TOPN_ && (tid == NT-1 || S[tid+1] < TOPN_)) s_g = tid;
    __syncthreads();
    if (tid == 0 && s_g < 0) s_cut = 0;
    if (s_g >= 0 && tid == s_g){
        int cum = (tid == NT-1) ? 0 : S[tid+1];
        int bin = tid*16 + 15;
        for (; bin >= tid*16; bin--){
            cum += hist[bin];
            if (cum >= TOPN_) break;
        }
        if (bin < tid*16) bin = tid*16;
        s_cut = bin;
    }
    __syncthreads();
    int cut = s_cut;

    int cnt1 = g_cnt1[b]; if (cnt1 > CAP1) cnt1 = CAP1;
    int per = (cnt1 + GSLICE-1) / GSLICE;
    int start = slice*per, end = min(start + per, cnt1);
    const unsigned long long* gc = g_cand1 + (size_t)b*CAP1;
    for (int i = start + tid; i < end; i += NT){
        unsigned long long key = gc[i];
        float sc = __uint_as_float((unsigned)(key >> 21));
        int bin = (int)((sc - HLO) * SCALE);
        if (bin > NBINS-1) bin = NBINS-1;
        bool win = (bin >= cut);
        unsigned bal = __ballot_sync(__activemask(), win);
        if (bal){
            int leader = __ffs(bal) - 1;
            int base = 0;
            if (lane == leader) base = atomicAdd(&g_cnt2[b], __popc(bal));
            base = __shfl_sync(__activemask(), base, leader);
            if (win){
                int pos = base + __popc(bal & ((1u << lane) - 1u));
                if (pos < SORTN) g_keys2[b*SORTN + pos] = key;
            }
        }
    }
}

// ------------------------- K3: sort + decode + NMS + output -------------------
// 1D grid of 64 blocks: b = blockIdx.x>>2, sub = blockIdx.x&3. The 4 blocks
// of a batch REDUNDANTLY sort + decode (identical, deterministic, parallel on
// different SMs), then each runs collect+NMS+output for its 20 classes
// (1 class/warp). Every output row is written by exactly one block (the class
// owner; empty rows by sub==0). Self-clean by sub==0.
__global__ void __launch_bounds__(1024, 1)
k_snd(const float* __restrict__ boxes, const float* __restrict__ loc,
      float* __restrict__ out){
    int b = blockIdx.x >> 2, sub = blockIdx.x & (NMSB-1);
    int tid = threadIdx.x, lane = tid & 31, wid = tid >> 5;

    __shared__ unsigned long long s_keys[SORTN];  // 16 KB
    __shared__ float4 s_det[TOPN_];               // 16 KB
    __shared__ unsigned char s_lab[TOPN_];
    __shared__ int   s_order[TOPN_];              // 4 KB
    __shared__ int   s_ccnt[CC];
    __shared__ int   s_coff[CC];

    int cnt2 = g_cnt2[b]; if (cnt2 > SORTN) cnt2 = SORTN;   // block-uniform
    bool big = (cnt2 > 1024);
    s_keys[tid] = (tid < cnt2) ? g_keys2[b*SORTN + tid] : 0ull;
    s_keys[1024 + tid] = (big && 1024 + tid < cnt2) ? g_keys2[b*SORTN + 1024 + tid] : 0ull;
    if (tid < CC) s_ccnt[tid] = 0;
    __syncthreads();

    if (!big){
        // ---- 1024-key hybrid bitonic, warps 0..15 own 64-element chunks ----
        if (wid < 16){
            int p0 = (wid << 6) + lane, p1 = p0 + 32;
            unsigned long long e0 = s_keys[p0], e1 = s_keys[p1];
            #pragma unroll
            for (int k = 2; k <= 32; k <<= 1){
                #pragma unroll
                for (int j = k >> 1; j > 0; j >>= 1){
                    e0 = regstep(e0, p0, k, j);
                    e1 = regstep(e1, p1, k, j);
                }
            }
            {   // k = 64: j=32 in-thread swap + shfl tail
                bool desc = ((p0 & 64) == 0);
                unsigned long long mx = (e0 > e1) ? e0 : e1;
                unsigned long long mn = (e0 > e1) ? e1 : e0;
                e0 = desc ? mx : mn;  e1 = desc ? mn : mx;
                #pragma unroll
                for (int j = 16; j > 0; j >>= 1){
                    e0 = regstep(e0, p0, 64, j);
                    e1 = regstep(e1, p1, 64, j);
                }
            }
            s_keys[p0] = e0; s_keys[p1] = e1;
        }
        for (int k = 128; k <= 1024; k <<= 1){
            for (int j = k >> 1; j >= 64; j >>= 1){
                __syncthreads();
                if (tid < 512){
                    int idx = ((tid & ~(j-1)) << 1) | (tid & (j-1));
                    int pr  = idx | j;
                    unsigned long long a = s_keys[idx], c = s_keys[pr];
                    bool up = (idx & k) == 0;
                    if (up ? (a < c) : (a > c)){ s_keys[idx] = c; s_keys[pr] = a; }
                }
            }
            __syncthreads();
            if (wid < 16){
                int p0 = (wid << 6) + lane, p1 = p0 + 32;
                unsigned long long e0 = s_keys[p0], e1 = s_keys[p1];
                bool desc = ((p0 & k) == 0);
                unsigned long long mx = (e0 > e1) ? e0 : e1;
                unsigned long long mn = (e0 > e1) ? e1 : e0;
                e0 = desc ? mx : mn;  e1 = desc ? mn : mx;
                #pragma unroll
                for (int j = 16; j > 0; j >>= 1){
                    e0 = regstep(e0, p0, k, j);
                    e1 = regstep(e1, p1, k, j);
                }
                s_keys[p0] = e0; s_keys[p1] = e1;
            }
        }
        __syncthreads();
    } else {
        // ---- full 2048-key hybrid bitonic (rare fallback) ----
        int p0 = (wid << 6) + lane, p1 = p0 + 32;
        unsigned long long e0 = s_keys[p0], e1 = s_keys[p1];
        #pragma unroll
        for (int k = 2; k <= 32; k <<= 1){
            #pragma unroll
            for (int j = k >> 1; j > 0; j >>= 1){
                e0 = regstep(e0, p0, k, j);
                e1 = regstep(e1, p1, k, j);
            }
        }
        {
            bool desc = ((p0 & 64) == 0);
            unsigned long long mx = (e0 > e1) ? e0 : e1;
            unsigned long long mn = (e0 > e1) ? e1 : e0;
            e0 = desc ? mx : mn;  e1 = desc ? mn : mx;
            #pragma unroll
            for (int j = 16; j > 0; j >>= 1){
                e0 = regstep(e0, p0, 64, j);
                e1 = regstep(e1, p1, 64, j);
            }
        }
        s_keys[p0] = e0; s_keys[p1] = e1;
        for (int k = 128; k <= SORTN; k <<= 1){
            for (int j = k >> 1; j >= 64; j >>= 1){
                __syncthreads();
                int idx = ((tid & ~(j-1)) << 1) | (tid & (j-1));
                int pr  = idx | j;
                unsigned long long a = s_keys[idx], c = s_keys[pr];
                bool up = (idx & k) == 0;
                if (up ? (a < c) : (a > c)){ s_keys[idx] = c; s_keys[pr] = a; }
            }
            __syncthreads();
            e0 = s_keys[p0]; e1 = s_keys[p1];
            bool desc = ((p0 & k) == 0);
            unsigned long long mx = (e0 > e1) ? e0 : e1;
            unsigned long long mn = (e0 > e1) ? e1 : e0;
            e0 = desc ? mx : mn;  e1 = desc ? mn : mx;
            #pragma unroll
            for (int j = 16; j > 0; j >>= 1){
                e0 = regstep(e0, p0, k, j);
                e1 = regstep(e1, p1, k, j);
            }
            s_keys[p0] = e0; s_keys[p1] = e1;
        }
        __syncthreads();
    }

    // ---- decode top-1000 (+ per-class counts in the same pass) ----
    if (tid < TOPN_){
        unsigned long long key = s_keys[tid];
        if (key == 0ull){
            s_det[tid] = make_float4(0.f,0.f,0.f,0.f);
            s_lab[tid] = 0;
            if (sub == 0){                       // empty rows: zero output
                int t = b*TOPN_ + tid;
                reinterpret_cast<float4*>(out)[t] = make_float4(0.f,0.f,0.f,0.f);
                out[BATCH*TOPN_*4 + t] = 0.0f;
                out[BATCH*TOPN_*5 + t] = 0.0f;
            }
        } else {
            unsigned idx = 0x1FFFFFu - (unsigned)(key & 0x1FFFFFu);
            int n = idx / CC, c = idx % CC;
            float4 pb = reinterpret_cast<const float4*>(boxes)[(size_t)b*NN + n];
            float2 l = reinterpret_cast<const float2*>(loc)[n];
            float x1 = fminf(fmaxf(l.x - pb.x, 0.0f), 1023.0f);
            float y1 = fminf(fmaxf(l.y - pb.y, 0.0f), 1023.0f);
            float x2 = fminf(fmaxf(l.x + pb.z, 0.0f), 1023.0f);
            float y2 = fminf(fmaxf(l.y + pb.w, 0.0f), 1023.0f);
            s_det[tid] = make_float4(x1, y1, x2, y2);
            s_lab[tid] = (unsigned char)(c + 1);
            atomicAdd(&s_ccnt[c], 1);
        }
    }
    // self-clean pipeline state (one block per batch does it)
    if (sub == 0){
        int* hist = g_hist + b*NBINS;
        #pragma unroll
        for (int k = 0; k < NBINS/1024; k++) hist[k*1024 + tid] = 0;
        if (tid == 0){ g_cnt1[b] = 0; g_cnt2[b] = 0; }
    }
    __syncthreads();
    if (tid == 0){
        int acc = 0;
        for (int c = 0; c < CC; c++){ s_coff[c] = acc; acc += s_ccnt[c]; }
    }
    __syncthreads();

    // ---- per-class greedy NMS for THIS block's 20 classes (1 class/warp) ----
    // Class offsets make cross-class IoU exactly 0. IoU on OFFSET boxes in
    // reference op order. Output rows written directly from the alive mask.
    if (wid < 20){
        int c = sub*20 + wid;                 // class id 0..79
        int off = s_coff[c];
        int m = 0;
        for (int k0 = 0; k0 < TOPN_; k0 += 32){
            int k = k0 + lane;
            bool match = (k < TOPN_) && (s_lab[k] == (unsigned char)(c+1));
            unsigned bal = __ballot_sync(0xffffffffu, match);
            if (match){
                int pos = m + __popc(bal & ((1u << lane) - 1u));
                s_order[off + pos] = k;       // ranks in descending-score order
            }
            m += __popc(bal);
        }
        float co = (float)(c+1) * 4096.0f;
        unsigned aliveM = 0xffffffffu;        // bit s2 => entry e = s2*32+lane alive
        int Sl = (m + 31) >> 5;
        for (int i = 0; i < m; i++){
            int owner = i & 31, slot = i >> 5;
            unsigned a = __shfl_sync(0xffffffffu, aliveM, owner);
            if (!((a >> slot) & 1u)) continue;         // warp-uniform
            float4 bi = s_det[s_order[off + i]];
            bi.x += co; bi.y += co; bi.z += co; bi.w += co;
            float ai = fmaxf(bi.z - bi.x, 0.f) * fmaxf(bi.w - bi.y, 0.f);
            for (int s2 = 0; s2 < Sl; s2++){
                int e = (s2 << 5) + lane;
                if (e > i && e < m && ((aliveM >> s2) & 1u)){
                    float4 bj = s_det[s_order[off + e]];
                    bj.x += co; bj.y += co; bj.z += co; bj.w += co;
                    float aj = fmaxf(bj.z - bj.x, 0.f) * fmaxf(bj.w - bj.y, 0.f);
                    float ix1 = fmaxf(bi.x, bj.x), iy1 = fmaxf(bi.y, bj.y);
                    float ix2 = fminf(bi.z, bj.z), iy2 = fminf(bi.w, bj.w);
                    float inter = fmaxf(ix2 - ix1, 0.f) * fmaxf(iy2 - iy1, 0.f);
                    float iou = inter / ((ai + aj - inter) + 1e-9f);
                    if (iou > 0.6f) aliveM &= ~(1u << s2);
                }
            }
        }
        // write this class's output rows
        for (int s2 = 0; s2 < Sl; s2++){
            int e = (s2 << 5) + lane;
            if (e < m){
                int k = s_order[off + e];
                int kp = (aliveM >> s2) & 1u;
                int t = b*TOPN_ + k;
                float kf = kp ? 1.0f : 0.0f;
                float4 d = s_det[k];
                reinterpret_cast<float4*>(out)[t] =
                    make_float4(d.x*kf, d.y*kf, d.z*kf, d.w*kf);
                out[BATCH*TOPN_*4 + t] =
                    kp ? __uint_as_float((unsigned)(s_keys[k] >> 21)) : 0.0f;
                out[BATCH*TOPN_*5 + t] = kp ? (float)(c+1) : 0.0f;
            }
        }
    }
}

// ------------------------- launch ---------------------------------------------
extern "C" void kernel_launch(void* const* d_in, const int* in_sizes, int n_in,
                              void* d_out, int out_size){
    const float* locations  = (const float*)d_in[0];
    const float* pred_cls   = (const float*)d_in[1];
    const float* pred_boxes = (const float*)d_in[2];
    const float* pred_ctr   = (const float*)d_in[3];
    float* out = (float*)d_out;

    k_pass1 <<<BATCH*BPB, NT>>>(pred_cls, pred_ctr);
    k_gather<<<BATCH*GSLICE, NT>>>();
    k_snd   <<<BATCH*NMSB, 1024>>>(pred_boxes, locations, out);
}